// round 12
// baseline (speedup 1.0000x reference)
#include <cuda_runtime.h>
#include <cuda_bf16.h>
#include <cstdint>
#include <cstring>

#define B_    4
#define T_    2048
#define DI    512
#define DO    512
#define NF    24
#define KDIM  (NF * DI)      // 12288, k = f*24 + n ordering
#define MROWS (B_ * T_)      // 8192
#define NBAND (MROWS / 128)  // 64

#define BM 128
#define BN 128
#define BK 64
#define NCHUNK (KDIM / BK)   // 192
#define STAGE_BYTES 65536    // Ahi 16K + Alo 16K + Bhi 16K + Blo 16K
#define NSTAGE 3
#define X_OFF  (NSTAGE * STAGE_BYTES)          // 3 x 4KB x-windows [128][8] fp32
#define PH_OFF (X_OFF + NSTAGE * 4096)         // phi [128][24] fp32 (12KB)
#define TILES_BYTES (PH_OFF + 12288)
#define SMEM_TOTAL (1024 + TILES_BYTES)        // 222208

// W bf16 hi/lo planes [o][f*24+n]; S checkpoints [band][k]
static __device__ __nv_bfloat16 g_Whi[(size_t)DO * KDIM];
static __device__ __nv_bfloat16 g_Wlo[(size_t)DO * KDIM];
static __device__ float         g_S0[(size_t)NBAND * KDIM];

// ---------------------------------------------------------------------------
// helpers (base sm_80/90 PTX only — sm_103 w/o 'a' rejects tcgen05; IMMA
// measured 4x slower than HMMA; bf16 3-pass mma.sync is the hardware floor)
// ---------------------------------------------------------------------------
__device__ __forceinline__ uint32_t smem_u32(const void* p) {
    uint32_t a;
    asm("{ .reg .u64 t; cvta.to.shared.u64 t, %1; cvt.u32.u64 %0, t; }"
        : "=r"(a) : "l"(p));
    return a;
}
__device__ __forceinline__ void cp16(uint32_t s, const void* g) {
    asm volatile("cp.async.cg.shared.global [%0], [%1], 16;\n"
                 :: "r"(s), "l"(g) : "memory");
}
#define CP_COMMIT() asm volatile("cp.async.commit_group;\n" ::: "memory")
#define CP_WAIT1()  asm volatile("cp.async.wait_group 1;\n" ::: "memory")
#define CP_WAIT0()  asm volatile("cp.async.wait_group 0;\n" ::: "memory")
#define SWZ(x) ((x) ^ (((x) >> 3) & 0x70))

__device__ __forceinline__ void ldsm4(uint32_t* r, uint32_t addr) {
    asm volatile("ldmatrix.sync.aligned.m8n8.x4.shared.b16 {%0,%1,%2,%3}, [%4];"
                 : "=r"(r[0]), "=r"(r[1]), "=r"(r[2]), "=r"(r[3]) : "r"(addr));
}
__device__ __forceinline__ void mma16816(float* d, const uint32_t* a,
                                         uint32_t b0, uint32_t b1) {
    asm volatile(
        "mma.sync.aligned.m16n8k16.row.col.f32.bf16.bf16.f32 "
        "{%0,%1,%2,%3}, {%4,%5,%6,%7}, {%8,%9}, {%0,%1,%2,%3};"
        : "+f"(d[0]), "+f"(d[1]), "+f"(d[2]), "+f"(d[3])
        : "r"(a[0]), "r"(a[1]), "r"(a[2]), "r"(a[3]), "r"(b0), "r"(b1));
}
__device__ __forceinline__ void sts16(uint32_t addr, unsigned short v) {
    asm volatile("st.shared.u16 [%0], %1;" :: "r"(addr), "h"(v));
}

// ---------------------------------------------------------------------------
// Kernel 0: convert M_weights (n,o,f) fp32 -> W_hi/W_lo bf16 [o][f*24+n]
// ---------------------------------------------------------------------------
__global__ void convert_w_kernel(const float* __restrict__ Mw) {
    size_t i = (size_t)blockIdx.x * 256 + threadIdx.x;   // over NF*DO*DI
    int f = (int)(i & (DI - 1));
    int o = (int)((i >> 9) & (DO - 1));
    int n = (int)(i >> 18);
    float v = Mw[i];
    __nv_bfloat16 hi = __float2bfloat16(v);
    float lo = v - __bfloat162float(hi);
    size_t d = (size_t)o * KDIM + (size_t)f * NF + n;
    g_Whi[d] = hi;
    g_Wlo[d] = __float2bfloat16(lo);
}

// ---------------------------------------------------------------------------
// Kernel 1: checkpoint scan — S before each 128-row band: g_S0[b*16+j][f*24+n]
// ---------------------------------------------------------------------------
__global__ void ckpt_kernel(const float* __restrict__ x,
                            const float* __restrict__ filt) {
    __shared__ float ph[T_];
    const int n = blockIdx.x;
    const int b = blockIdx.y;
    const int f = blockIdx.z * 128 + threadIdx.x;

    for (int t = threadIdx.x; t < T_; t += 128)
        ph[t] = filt[t * NF + n];
    __syncthreads();

    const float* xb = x + (size_t)b * T_ * DI + f;
    float s = 0.f;
    for (int t0 = 0; t0 < T_; t0 += 8) {
        if ((t0 & 127) == 0)
            g_S0[(size_t)(b * 16 + (t0 >> 7)) * KDIM + f * NF + n] = s;
        float xv[8];
#pragma unroll
        for (int u = 0; u < 8; u++)
            xv[u] = xb[(size_t)(t0 + u) * DI];
#pragma unroll
        for (int u = 0; u < 8; u++)
            s = fmaf(ph[t0 + u], xv[u], s);
    }
}

// ---------------------------------------------------------------------------
// Kernel 2: fused scan + split-bf16 GEMM (R7 tensor config: 128x128, 8 warps)
// A tiles are PRODUCED in-CTA from x + checkpoints; B via cp.async.
// ---------------------------------------------------------------------------
__device__ __forceinline__ void load_BX(uint32_t tiles, int stage, int ch,
                                        const __nv_bfloat16* Bh,
                                        const __nv_bfloat16* Bl,
                                        const float* __restrict__ x,
                                        int m0, int tid) {
    const uint32_t st = tiles + stage * STAGE_BYTES;
    const int k0 = ch * BK;
    // B planes: 128 rows(o) x 128B
#pragma unroll
    for (int j = 0; j < 4; j++) {
        const int u = j * 256 + tid;
        const int r = u >> 3, sg = u & 7;
        const uint32_t so = SWZ((uint32_t)(r * 128 + sg * 16));
        const size_t go = (size_t)r * KDIM + k0 + sg * 8;
        cp16(st + 32768 + so, Bh + go);
        cp16(st + 49152 + so, Bl + go);
    }
    // x window [128 t][8 f], f0 4-aligned, clamped to array end
    int f0 = (k0 / NF) & ~3;
    if (f0 > DI - 8) f0 = DI - 8;
    const int row = tid >> 1, half = tid & 1;
    cp16(tiles + X_OFF + stage * 4096 + row * 32 + half * 16,
         x + (size_t)(m0 + row) * DI + f0 + half * 4);
    CP_COMMIT();
}

__global__ __launch_bounds__(256, 1) void gemm_kernel(
        float* __restrict__ C,
        const float* __restrict__ x,
        const float* __restrict__ filt) {
    extern __shared__ char smem[];
    const uint32_t sb    = smem_u32(smem);
    const uint32_t tiles = (sb + 1023) & ~1023u;
    char* tp = smem + (tiles - sb);
    float* phf = (float*)(tp + PH_OFF);               // [128][24]

    const int tid  = threadIdx.x;
    const int wid  = tid >> 5;
    const int lane = tid & 31;
    const int band = blockIdx.y;
    const int m0 = band * BM;
    const int n0 = blockIdx.x * BN;
    const int wm = (wid >> 2) * 64;
    const int wn = (wid & 3) * 32;
    const int lr = lane & 15;
    const int lc = lane >> 4;
    // chain assignment: 64 chains x 4 segs
    const int cch = tid >> 2;       // chain 0..63
    const int seg = tid & 3;        // t segment (32 each)
    const int tband = (band & 15) * 128;

    const __nv_bfloat16* Bh = g_Whi + (size_t)n0 * KDIM;
    const __nv_bfloat16* Bl = g_Wlo + (size_t)n0 * KDIM;

    // stage phi tile
    for (int i = tid; i < 128 * NF; i += 256)
        phf[i] = filt[(tband + i / NF) * NF + (i % NF)];

    float acc[4][4][4];
#pragma unroll
    for (int i = 0; i < 4; i++)
#pragma unroll
        for (int j = 0; j < 4; j++)
#pragma unroll
            for (int r = 0; r < 4; r++) acc[i][j][r] = 0.f;

    load_BX(tiles, 0, 0, Bh, Bl, x, m0, tid);
    load_BX(tiles, 1, 1, Bh, Bl, x, m0, tid);

    // ---- produce A[0] (full) ----
    {
        const int kk = cch;                         // chunk 0: k = c
        const int nn = kk % NF;
        int f0 = 0;                                 // chunk 0 window base
        const int fw = kk / NF - f0;
        CP_WAIT1();                                 // group 0 (B0 + x0) done
        __syncthreads();                            // x0, phi visible
        const float* xsf = (const float*)(tp + X_OFF);
        float part = 0.f;
#pragma unroll 8
        for (int i = 0; i < 32; i++) {
            const int t = seg * 32 + i;
            part = fmaf(phf[t * NF + nn], xsf[t * 8 + fw], part);
        }
        float s = g_S0[(size_t)band * KDIM + kk];
#pragma unroll
        for (int j = 0; j < 3; j++) {
            float pj = __shfl_sync(0xffffffffu, part, (lane & ~3) + j);
            if (j < seg) s += pj;
        }
        const uint32_t ah = tiles, al = tiles + 16384;
#pragma unroll 8
        for (int i = 0; i < 32; i++) {
            const int t = seg * 32 + i;
            const float p = phf[t * NF + nn];
            s = fmaf(p, xsf[t * 8 + fw], s);
            const float v = p * s;
            __nv_bfloat16 hi = __float2bfloat16(v);
            __nv_bfloat16 lo = __float2bfloat16(v - __bfloat162float(hi));
            unsigned short hb, lb;
            memcpy(&hb, &hi, 2); memcpy(&lb, &lo, 2);
            const uint32_t so = SWZ((uint32_t)(t * 128 + cch * 2));
            sts16(ah + so, hb);
            sts16(al + so, lb);
        }
    }

    for (int ch = 0; ch < NCHUNK; ch++) {
        CP_WAIT0();
        __syncthreads();     // A[ch], B[ch], x[ch+1] all visible

        if (ch + 2 < NCHUNK)
            load_BX(tiles, (ch + 2) % NSTAGE, ch + 2, Bh, Bl, x, m0, tid);

        // ---- produce setup for chunk ch+1 (clamped; garbage harmless at end)
        const int s2  = (ch + 1) % NSTAGE;
        const int chc = (ch + 1 < NCHUNK) ? ch + 1 : ch;
        const int kk  = chc * BK + cch;
        const int nn  = kk % NF;
        int f0 = ((chc * BK) / NF) & ~3;
        if (f0 > DI - 8) f0 = DI - 8;
        const int fw = kk / NF - f0;
        const float* xsf = (const float*)(tp + X_OFF + s2 * 4096);
        const uint32_t ah = tiles + s2 * STAGE_BYTES;
        const uint32_t al = ah + 16384;

        float part = 0.f;
#pragma unroll 8
        for (int i = 0; i < 32; i++) {
            const int t = seg * 32 + i;
            part = fmaf(phf[t * NF + nn], xsf[t * 8 + fw], part);
        }
        float s = g_S0[(size_t)band * KDIM + kk];
#pragma unroll
        for (int j = 0; j < 3; j++) {
            float pj = __shfl_sync(0xffffffffu, part, (lane & ~3) + j);
            if (j < seg) s += pj;
        }

        const uint32_t base = tiles + (ch % NSTAGE) * STAGE_BYTES;
#pragma unroll
        for (int ks = 0; ks < 4; ks++) {
            uint32_t aH[16], aL[16], bH[8], bL[8];
            const uint32_t kb = (uint32_t)(ks * 32 + lc * 16);
#pragma unroll
            for (int i = 0; i < 4; i++) {
                const uint32_t off = SWZ((uint32_t)((wm + i * 16 + lr) * 128) + kb);
                ldsm4(aH + 4 * i, base +         off);
                ldsm4(aL + 4 * i, base + 16384 + off);
            }
#pragma unroll
            for (int j = 0; j < 2; j++) {
                const uint32_t off = SWZ((uint32_t)((wn + j * 16 + lr) * 128) + kb);
                ldsm4(bH + 4 * j, base + 32768 + off);
                ldsm4(bL + 4 * j, base + 49152 + off);
            }
            // 3 split passes: hi*hi, hi*lo, lo*hi
#pragma unroll
            for (int i = 0; i < 4; i++) {
#pragma unroll
                for (int j = 0; j < 2; j++) {
                    mma16816(acc[i][2 * j],     aH + 4 * i, bH[4 * j],     bH[4 * j + 2]);
                    mma16816(acc[i][2 * j + 1], aH + 4 * i, bH[4 * j + 1], bH[4 * j + 3]);
                    mma16816(acc[i][2 * j],     aH + 4 * i, bL[4 * j],     bL[4 * j + 2]);
                    mma16816(acc[i][2 * j + 1], aH + 4 * i, bL[4 * j + 1], bL[4 * j + 3]);
                    mma16816(acc[i][2 * j],     aL + 4 * i, bH[4 * j],     bH[4 * j + 2]);
                    mma16816(acc[i][2 * j + 1], aL + 4 * i, bH[4 * j + 1], bH[4 * j + 3]);
                }
            }
            // ---- interleaved A-production slice: 8 chain steps ----
#pragma unroll
            for (int i = 0; i < 8; i++) {
                const int t = seg * 32 + ks * 8 + i;
                const float p = phf[t * NF + nn];
                s = fmaf(p, xsf[t * 8 + fw], s);
                const float v = p * s;
                __nv_bfloat16 hi = __float2bfloat16(v);
                __nv_bfloat16 lo = __float2bfloat16(v - __bfloat162float(hi));
                unsigned short hb, lb;
                memcpy(&hb, &hi, 2); memcpy(&lb, &lo, 2);
                const uint32_t so = SWZ((uint32_t)(t * 128 + cch * 2));
                sts16(ah + so, hb);
                sts16(al + so, lb);
            }
        }
    }

    // Epilogue: d0,d1 at (row=lane/4, col=2*(lane%4)); d2,d3 at row+8.
    const int er = lane >> 2;
    const int ec = (lane & 3) * 2;
#pragma unroll
    for (int i = 0; i < 4; i++) {
#pragma unroll
        for (int jj = 0; jj < 4; jj++) {
            const int row = m0 + wm + i * 16 + er;
            const int col = n0 + wn + jj * 8 + ec;
            *(float2*)(C + (size_t)row * DO + col) =
                make_float2(acc[i][jj][0], acc[i][jj][1]);
            *(float2*)(C + (size_t)(row + 8) * DO + col) =
                make_float2(acc[i][jj][2], acc[i][jj][3]);
        }
    }
}

// ---------------------------------------------------------------------------
extern "C" void kernel_launch(void* const* d_in, const int* in_sizes, int n_in,
                              void* d_out, int out_size) {
    (void)in_sizes; (void)n_in; (void)out_size;
    const float* x    = (const float*)d_in[0];   // (B, T, DI)
    const float* filt = (const float*)d_in[1];   // (T, NF)
    const float* Mw   = (const float*)d_in[2];   // (NF, DO, DI)
    float*       out  = (float*)d_out;           // (B, T, DO)

    cudaFuncSetAttribute(gemm_kernel,
                         cudaFuncAttributeMaxDynamicSharedMemorySize, SMEM_TOTAL);

    convert_w_kernel<<<(NF * DO * DI) / 256, 256>>>(Mw);
    ckpt_kernel<<<dim3(NF, B_, DI / 128), 128>>>(x, filt);
    gemm_kernel<<<dim3(DO / BN, MROWS / BM), 256, SMEM_TOTAL>>>(out, x, filt);
}

// round 14
// speedup vs baseline: 1.6726x; 1.6726x over previous
#include <cuda_runtime.h>
#include <cuda_bf16.h>
#include <cstdint>

#define B_    4
#define T_    2048
#define DI    512
#define DO    512
#define NF    24
#define KDIM  (NF * DI)      // 12288
#define MROWS (B_ * T_)      // 8192

#define BM 128
#define BN 128
#define BK 64
#define KSPLIT 4
#define NCHUNK_SPLIT (KDIM / BK / KSPLIT)   // 48 chunks per CTA
#define STAGE_BYTES 65536    // Ahi 16K + Alo 16K + Bhi 16K + Blo 16K
#define NSTAGE 3
#define SMEM_TOTAL (NSTAGE * STAGE_BYTES + 1024)

// bf16 hi/lo split operands
static __device__ __nv_bfloat16 g_Ahi[(size_t)MROWS * KDIM];
static __device__ __nv_bfloat16 g_Alo[(size_t)MROWS * KDIM];
static __device__ __nv_bfloat16 g_Whi[(size_t)DO * KDIM];   // [o][n*DI+f]  (col-major B)
static __device__ __nv_bfloat16 g_Wlo[(size_t)DO * KDIM];
// split-K partials [KSPLIT][MROWS][DO] fp32 (67 MB)
static __device__ float g_part[(size_t)KSPLIT * MROWS * DO];

// ---------------------------------------------------------------------------
// helpers (base sm_80/90 PTX only — sm_103 w/o 'a' rejects tcgen05; IMMA
// measured 4x slower than HMMA; 3-pass bf16 mma.sync is the hardware floor)
// ---------------------------------------------------------------------------
__device__ __forceinline__ uint32_t smem_u32(const void* p) {
    uint32_t a;
    asm("{ .reg .u64 t; cvta.to.shared.u64 t, %1; cvt.u32.u64 %0, t; }"
        : "=r"(a) : "l"(p));
    return a;
}
__device__ __forceinline__ void cp16(uint32_t s, const void* g) {
    asm volatile("cp.async.cg.shared.global [%0], [%1], 16;\n"
                 :: "r"(s), "l"(g) : "memory");
}
#define CP_COMMIT() asm volatile("cp.async.commit_group;\n" ::: "memory")
#define CP_WAIT1()  asm volatile("cp.async.wait_group 1;\n" ::: "memory")
#define CP_WAIT0()  asm volatile("cp.async.wait_group 0;\n" ::: "memory")
#define SWZ(x) ((x) ^ (((x) >> 3) & 0x70))

__device__ __forceinline__ void ldsm4(uint32_t* r, uint32_t addr) {
    asm volatile("ldmatrix.sync.aligned.m8n8.x4.shared.b16 {%0,%1,%2,%3}, [%4];"
                 : "=r"(r[0]), "=r"(r[1]), "=r"(r[2]), "=r"(r[3]) : "r"(addr));
}
__device__ __forceinline__ void mma16816(float* d, const uint32_t* a,
                                         uint32_t b0, uint32_t b1) {
    asm volatile(
        "mma.sync.aligned.m16n8k16.row.col.f32.bf16.bf16.f32 "
        "{%0,%1,%2,%3}, {%4,%5,%6,%7}, {%8,%9}, {%0,%1,%2,%3};"
        : "+f"(d[0]), "+f"(d[1]), "+f"(d[2]), "+f"(d[3])
        : "r"(a[0]), "r"(a[1]), "r"(a[2]), "r"(a[3]), "r"(b0), "r"(b1));
}

// ---------------------------------------------------------------------------
// Kernel 0: convert M_weights (n,o,f) fp32 -> W_hi/W_lo bf16 [o][n*DI+f]
// ---------------------------------------------------------------------------
__global__ void convert_w_kernel(const float* __restrict__ Mw) {
    size_t i = (size_t)blockIdx.x * 256 + threadIdx.x;   // over NF*DO*DI
    int f = (int)(i & (DI - 1));
    int o = (int)((i >> 9) & (DO - 1));
    int n = (int)(i >> 18);
    float v = Mw[i];
    __nv_bfloat16 hi = __float2bfloat16(v);
    float lo = v - __bfloat162float(hi);
    size_t d = (size_t)o * KDIM + (size_t)n * DI + f;
    g_Whi[d] = hi;
    g_Wlo[d] = __float2bfloat16(lo);
}

// ---------------------------------------------------------------------------
// Kernel 1: weighted causal scan -> A_hi/A_lo bf16 [(b*T+t)][n*DI+f]
// ---------------------------------------------------------------------------
__global__ void scan_kernel(const float* __restrict__ x,
                            const float* __restrict__ filt) {
    __shared__ float ph[T_];
    const int n = blockIdx.x;
    const int b = blockIdx.y;
    const int f = blockIdx.z * 128 + threadIdx.x;

    for (int t = threadIdx.x; t < T_; t += 128)
        ph[t] = filt[t * NF + n];
    __syncthreads();

    const float* xb = x + (size_t)b * T_ * DI + f;
    const size_t base = (size_t)b * T_ * KDIM + (size_t)n * DI + f;

    float s = 0.f;
    for (int t0 = 0; t0 < T_; t0 += 8) {
        float xv[8];
#pragma unroll
        for (int u = 0; u < 8; u++)
            xv[u] = xb[(size_t)(t0 + u) * DI];
#pragma unroll
        for (int u = 0; u < 8; u++) {
            const float p = ph[t0 + u];
            s = fmaf(p, xv[u], s);
            const float v = p * s;
            const __nv_bfloat16 hi = __float2bfloat16(v);
            const float lo = v - __bfloat162float(hi);
            const size_t idx = base + (size_t)(t0 + u) * KDIM;
            g_Ahi[idx] = hi;
            g_Alo[idx] = __float2bfloat16(lo);
        }
    }
}

// ---------------------------------------------------------------------------
// Kernel 2: split-bf16 GEMM via mma.sync — R7 champion config + split-K/4.
// CTA 128x128, 256 threads (8 warps 2x4, 64x32 warp tiles), 3-stage cp.async.
// 1024 CTAs (6.92 waves, imbalance 1.012) each do 48 K-chunks; partials out.
// ---------------------------------------------------------------------------
__device__ __forceinline__ void load_chunk(uint32_t tiles, int stage,
                                           const __nv_bfloat16* Ah,
                                           const __nv_bfloat16* Al,
                                           const __nv_bfloat16* Bh,
                                           const __nv_bfloat16* Bl,
                                           int k0, int tid) {
    const uint32_t s = tiles + stage * STAGE_BYTES;
    const __nv_bfloat16* ah = Ah + k0;
    const __nv_bfloat16* al = Al + k0;
    const __nv_bfloat16* bh = Bh + k0;
    const __nv_bfloat16* bl = Bl + k0;
    // each subtile: 128 rows x 128B = 1024 x 16B units; 256 threads -> 4 each
#pragma unroll
    for (int j = 0; j < 4; j++) {
        const int u = j * 256 + tid;
        const int r = u >> 3, seg = u & 7;
        const uint32_t so = SWZ((uint32_t)(r * 128 + seg * 16));
        const size_t go = (size_t)r * KDIM + seg * 8;
        cp16(s +         so, ah + go);
        cp16(s + 16384 + so, al + go);
        cp16(s + 32768 + so, bh + go);
        cp16(s + 49152 + so, bl + go);
    }
    CP_COMMIT();
}

__global__ __launch_bounds__(256, 1) void gemm_kernel() {
    extern __shared__ char smem[];
    const uint32_t sb    = smem_u32(smem);
    const uint32_t tiles = (sb + 1023) & ~1023u;

    const int tid  = threadIdx.x;
    const int wid  = tid >> 5;
    const int lane = tid & 31;
    const int m0 = blockIdx.y * BM;
    const int n0 = blockIdx.x * BN;
    const int z  = blockIdx.z;                     // K-split index
    const int c0 = z * NCHUNK_SPLIT;               // first chunk
    const int wm = (wid >> 2) * 64;
    const int wn = (wid & 3) * 32;
    const int lr = lane & 15;
    const int lc = lane >> 4;

    const __nv_bfloat16* Ah = g_Ahi + (size_t)m0 * KDIM;
    const __nv_bfloat16* Al = g_Alo + (size_t)m0 * KDIM;
    const __nv_bfloat16* Bh = g_Whi + (size_t)n0 * KDIM;
    const __nv_bfloat16* Bl = g_Wlo + (size_t)n0 * KDIM;

    float acc[4][4][4];                 // [m16-tile][n8-tile][frag]
#pragma unroll
    for (int i = 0; i < 4; i++)
#pragma unroll
        for (int j = 0; j < 4; j++)
#pragma unroll
            for (int r = 0; r < 4; r++) acc[i][j][r] = 0.f;

    load_chunk(tiles, 0, Ah, Al, Bh, Bl, c0 * BK, tid);
    load_chunk(tiles, 1, Ah, Al, Bh, Bl, (c0 + 1) * BK, tid);

    for (int ch = 0; ch < NCHUNK_SPLIT; ch++) {
        if (ch >= NCHUNK_SPLIT - 2) { CP_WAIT0(); } else { CP_WAIT1(); }
        __syncthreads();

        // stage (ch+2)%3 == (ch-1)%3 fully consumed pre-barrier: refill now so
        // the async engine runs underneath the MMA block.
        if (ch + 2 < NCHUNK_SPLIT)
            load_chunk(tiles, (ch + 2) % NSTAGE, Ah, Al, Bh, Bl,
                       (c0 + ch + 2) * BK, tid);

        const uint32_t base = tiles + (ch % NSTAGE) * STAGE_BYTES;
#pragma unroll
        for (int ks = 0; ks < 4; ks++) {
            uint32_t aH[16], aL[16], bH[8], bL[8];
            const uint32_t kb = (uint32_t)(ks * 32 + lc * 16);
#pragma unroll
            for (int i = 0; i < 4; i++) {
                const uint32_t off = SWZ((uint32_t)((wm + i * 16 + lr) * 128) + kb);
                ldsm4(aH + 4 * i, base +         off);
                ldsm4(aL + 4 * i, base + 16384 + off);
            }
#pragma unroll
            for (int j = 0; j < 2; j++) {
                const uint32_t off = SWZ((uint32_t)((wn + j * 16 + lr) * 128) + kb);
                ldsm4(bH + 4 * j, base + 32768 + off);
                ldsm4(bL + 4 * j, base + 49152 + off);
            }
            // 3 split passes: hi*hi, hi*lo, lo*hi (lo*lo dropped, ~2^-16)
#pragma unroll
            for (int i = 0; i < 4; i++) {
#pragma unroll
                for (int j = 0; j < 2; j++) {
                    // x4 ldmatrix: r0=(rows0-7,k0-7), r1=(rows8-15,k0-7),
                    //              r2=(rows0-7,k8-15), r3=(rows8-15,k8-15)
                    mma16816(acc[i][2 * j],     aH + 4 * i, bH[4 * j],     bH[4 * j + 2]);
                    mma16816(acc[i][2 * j + 1], aH + 4 * i, bH[4 * j + 1], bH[4 * j + 3]);
                    mma16816(acc[i][2 * j],     aH + 4 * i, bL[4 * j],     bL[4 * j + 2]);
                    mma16816(acc[i][2 * j + 1], aH + 4 * i, bL[4 * j + 1], bL[4 * j + 3]);
                    mma16816(acc[i][2 * j],     aL + 4 * i, bH[4 * j],     bH[4 * j + 2]);
                    mma16816(acc[i][2 * j + 1], aL + 4 * i, bH[4 * j + 1], bH[4 * j + 3]);
                }
            }
        }
    }

    // Epilogue: plain coalesced partial stores (no atomics).
    float* P = g_part + (size_t)z * MROWS * DO;
    const int er = lane >> 2;
    const int ec = (lane & 3) * 2;
#pragma unroll
    for (int i = 0; i < 4; i++) {
#pragma unroll
        for (int jj = 0; jj < 4; jj++) {
            const int row = m0 + wm + i * 16 + er;
            const int col = n0 + wn + jj * 8 + ec;
            *(float2*)(P + (size_t)row * DO + col) =
                make_float2(acc[i][jj][0], acc[i][jj][1]);
            *(float2*)(P + (size_t)(row + 8) * DO + col) =
                make_float2(acc[i][jj][2], acc[i][jj][3]);
        }
    }
}

// ---------------------------------------------------------------------------
// Kernel 3: reduce 4 split-K partial planes into C (grid-stride, robust)
// ---------------------------------------------------------------------------
__global__ void reduce_kernel(float* __restrict__ C) {
    const size_t NPL = (size_t)MROWS * DO;
    const size_t stride = (size_t)gridDim.x * blockDim.x * 4;
    for (size_t i = ((size_t)blockIdx.x * blockDim.x + threadIdx.x) * 4;
         i < NPL; i += stride) {
        float4 a = *(const float4*)(g_part + i);
        float4 b = *(const float4*)(g_part + NPL + i);
        float4 c = *(const float4*)(g_part + 2 * NPL + i);
        float4 d = *(const float4*)(g_part + 3 * NPL + i);
        float4 o;
        o.x = (a.x + b.x) + (c.x + d.x);
        o.y = (a.y + b.y) + (c.y + d.y);
        o.z = (a.z + b.z) + (c.z + d.z);
        o.w = (a.w + b.w) + (c.w + d.w);
        *(float4*)(C + i) = o;
    }
}

// ---------------------------------------------------------------------------
extern "C" void kernel_launch(void* const* d_in, const int* in_sizes, int n_in,
                              void* d_out, int out_size) {
    (void)in_sizes; (void)n_in; (void)out_size;
    const float* x    = (const float*)d_in[0];   // (B, T, DI)
    const float* filt = (const float*)d_in[1];   // (T, NF)
    const float* Mw   = (const float*)d_in[2];   // (NF, DO, DI)
    float*       out  = (float*)d_out;           // (B, T, DO)

    cudaFuncSetAttribute(gemm_kernel,
                         cudaFuncAttributeMaxDynamicSharedMemorySize, SMEM_TOTAL);

    convert_w_kernel<<<(NF * DO * DI) / 256, 256>>>(Mw);
    scan_kernel<<<dim3(NF, B_, DI / 128), 128>>>(x, filt);
    gemm_kernel<<<dim3(DO / BN, MROWS / BM, KSPLIT), 256, SMEM_TOTAL>>>();
    reduce_kernel<<<1024, 256>>>(out);
}

// round 15
// speedup vs baseline: 2.0102x; 1.2018x over previous
#include <cuda_runtime.h>
#include <cuda_bf16.h>
#include <cstdint>

#define B_    4
#define T_    2048
#define DI    512
#define DO    512
#define NF    24
#define KDIM  (NF * DI)      // 12288
#define MROWS (B_ * T_)      // 8192
#define NBANDT 16            // t-bands per sequence (128 steps each)

#define BM 128
#define BN 128
#define BK 64
#define KSPLIT 4
#define NCHUNK_SPLIT (KDIM / BK / KSPLIT)   // 48 chunks per CTA
#define STAGE_BYTES 65536    // Ahi 16K + Alo 16K + Bhi 16K + Blo 16K
#define NSTAGE 3
#define SMEM_TOTAL (NSTAGE * STAGE_BYTES + 1024)

// bf16 hi/lo split operands
static __device__ __nv_bfloat16 g_Ahi[(size_t)MROWS * KDIM];
static __device__ __nv_bfloat16 g_Alo[(size_t)MROWS * KDIM];
static __device__ __nv_bfloat16 g_Whi[(size_t)DO * KDIM];   // [o][n*DI+f]  (col-major B)
static __device__ __nv_bfloat16 g_Wlo[(size_t)DO * KDIM];
// split-K partials [KSPLIT][MROWS][DO] fp32 (67 MB)
static __device__ float g_part[(size_t)KSPLIT * MROWS * DO];
// scan band sums / exclusive prefixes [B*16][KDIM] fp32 (3.1 MB each)
static __device__ float g_band[(size_t)B_ * NBANDT * KDIM];
static __device__ float g_S0[(size_t)B_ * NBANDT * KDIM];

// ---------------------------------------------------------------------------
// helpers (base sm_80/90 PTX only — sm_103 w/o 'a' rejects tcgen05; IMMA
// measured 4x slower than HMMA; 3-pass bf16 mma.sync is the hardware floor)
// ---------------------------------------------------------------------------
__device__ __forceinline__ uint32_t smem_u32(const void* p) {
    uint32_t a;
    asm("{ .reg .u64 t; cvta.to.shared.u64 t, %1; cvt.u32.u64 %0, t; }"
        : "=r"(a) : "l"(p));
    return a;
}
__device__ __forceinline__ void cp16(uint32_t s, const void* g) {
    asm volatile("cp.async.cg.shared.global [%0], [%1], 16;\n"
                 :: "r"(s), "l"(g) : "memory");
}
#define CP_COMMIT() asm volatile("cp.async.commit_group;\n" ::: "memory")
#define CP_WAIT1()  asm volatile("cp.async.wait_group 1;\n" ::: "memory")
#define CP_WAIT0()  asm volatile("cp.async.wait_group 0;\n" ::: "memory")
#define SWZ(x) ((x) ^ (((x) >> 3) & 0x70))

__device__ __forceinline__ void ldsm4(uint32_t* r, uint32_t addr) {
    asm volatile("ldmatrix.sync.aligned.m8n8.x4.shared.b16 {%0,%1,%2,%3}, [%4];"
                 : "=r"(r[0]), "=r"(r[1]), "=r"(r[2]), "=r"(r[3]) : "r"(addr));
}
__device__ __forceinline__ void mma16816(float* d, const uint32_t* a,
                                         uint32_t b0, uint32_t b1) {
    asm volatile(
        "mma.sync.aligned.m16n8k16.row.col.f32.bf16.bf16.f32 "
        "{%0,%1,%2,%3}, {%4,%5,%6,%7}, {%8,%9}, {%0,%1,%2,%3};"
        : "+f"(d[0]), "+f"(d[1]), "+f"(d[2]), "+f"(d[3])
        : "r"(a[0]), "r"(a[1]), "r"(a[2]), "r"(a[3]), "r"(b0), "r"(b1));
}

// ---------------------------------------------------------------------------
// Kernel 0: convert M_weights (n,o,f) fp32 -> W_hi/W_lo bf16 [o][n*DI+f]
// ---------------------------------------------------------------------------
__global__ void convert_w_kernel(const float* __restrict__ Mw) {
    size_t i = (size_t)blockIdx.x * 256 + threadIdx.x;   // over NF*DO*DI
    int f = (int)(i & (DI - 1));
    int o = (int)((i >> 9) & (DO - 1));
    int n = (int)(i >> 18);
    float v = Mw[i];
    __nv_bfloat16 hi = __float2bfloat16(v);
    float lo = v - __bfloat162float(hi);
    size_t d = (size_t)o * KDIM + (size_t)n * DI + f;
    g_Whi[d] = hi;
    g_Wlo[d] = __float2bfloat16(lo);
}

// ---------------------------------------------------------------------------
// Scan phase A: per-band sums  bandsum[b*16+j][n*DI+f] = sum_{t in band} phi*x
// grid (NF, B_, 64): z = band*4 + fchunk; block 128
// ---------------------------------------------------------------------------
__global__ void band_sum_kernel(const float* __restrict__ x,
                                const float* __restrict__ filt) {
    __shared__ float ph[128];
    const int n    = blockIdx.x;
    const int b    = blockIdx.y;
    const int band = blockIdx.z >> 2;
    const int fc   = blockIdx.z & 3;
    const int f    = fc * 128 + threadIdx.x;
    const int t0   = band * 128;

    if (threadIdx.x < 128)
        ph[threadIdx.x] = filt[(t0 + threadIdx.x) * NF + n];
    __syncthreads();

    const float* xb = x + ((size_t)b * T_ + t0) * DI + f;
    float s = 0.f;
#pragma unroll 8
    for (int i = 0; i < 128; i++)
        s = fmaf(ph[i], xb[(size_t)i * DI], s);
    g_band[(size_t)(b * NBANDT + band) * KDIM + n * DI + f] = s;
}

// ---------------------------------------------------------------------------
// Scan phase B: exclusive prefix over the 16 bands of each (b,k) chain
// ---------------------------------------------------------------------------
__global__ void band_prefix_kernel() {
    const size_t c = (size_t)blockIdx.x * 256 + threadIdx.x;  // over B_*KDIM
    const int b = (int)(c / KDIM);
    const int k = (int)(c % KDIM);
    float run = 0.f;
#pragma unroll
    for (int j = 0; j < NBANDT; j++) {
        const size_t idx = (size_t)(b * NBANDT + j) * KDIM + k;
        const float v = g_band[idx];
        g_S0[idx] = run;
        run += v;
    }
}

// ---------------------------------------------------------------------------
// Scan phase C: within-band scan -> A_hi/A_lo bf16 [(b*T+t)][n*DI+f]
// grid (NF, B_, 64): z = band*4 + fchunk; block 128
// ---------------------------------------------------------------------------
__global__ void scan_kernel(const float* __restrict__ x,
                            const float* __restrict__ filt) {
    __shared__ float ph[128];
    const int n    = blockIdx.x;
    const int b    = blockIdx.y;
    const int band = blockIdx.z >> 2;
    const int fc   = blockIdx.z & 3;
    const int f    = fc * 128 + threadIdx.x;
    const int t0   = band * 128;

    if (threadIdx.x < 128)
        ph[threadIdx.x] = filt[(t0 + threadIdx.x) * NF + n];
    __syncthreads();

    const float* xb = x + ((size_t)b * T_ + t0) * DI + f;
    const size_t base = ((size_t)b * T_ + t0) * KDIM + (size_t)n * DI + f;

    float s = g_S0[(size_t)(b * NBANDT + band) * KDIM + n * DI + f];
#pragma unroll 4
    for (int i0 = 0; i0 < 128; i0 += 8) {
        float xv[8];
#pragma unroll
        for (int u = 0; u < 8; u++)
            xv[u] = xb[(size_t)(i0 + u) * DI];
#pragma unroll
        for (int u = 0; u < 8; u++) {
            const float p = ph[i0 + u];
            s = fmaf(p, xv[u], s);
            const float v = p * s;
            const __nv_bfloat16 hi = __float2bfloat16(v);
            const float lo = v - __bfloat162float(hi);
            const size_t idx = base + (size_t)(i0 + u) * KDIM;
            g_Ahi[idx] = hi;
            g_Alo[idx] = __float2bfloat16(lo);
        }
    }
}

// ---------------------------------------------------------------------------
// Kernel 2: split-bf16 GEMM via mma.sync — champion config + split-K/4.
// CTA 128x128, 256 threads (8 warps 2x4, 64x32 warp tiles), 3-stage cp.async.
// 1024 CTAs (6.92 waves, imbalance 1.012) each do 48 K-chunks; partials out.
// ---------------------------------------------------------------------------
__device__ __forceinline__ void load_chunk(uint32_t tiles, int stage,
                                           const __nv_bfloat16* Ah,
                                           const __nv_bfloat16* Al,
                                           const __nv_bfloat16* Bh,
                                           const __nv_bfloat16* Bl,
                                           int k0, int tid) {
    const uint32_t s = tiles + stage * STAGE_BYTES;
    const __nv_bfloat16* ah = Ah + k0;
    const __nv_bfloat16* al = Al + k0;
    const __nv_bfloat16* bh = Bh + k0;
    const __nv_bfloat16* bl = Bl + k0;
    // each subtile: 128 rows x 128B = 1024 x 16B units; 256 threads -> 4 each
#pragma unroll
    for (int j = 0; j < 4; j++) {
        const int u = j * 256 + tid;
        const int r = u >> 3, seg = u & 7;
        const uint32_t so = SWZ((uint32_t)(r * 128 + seg * 16));
        const size_t go = (size_t)r * KDIM + seg * 8;
        cp16(s +         so, ah + go);
        cp16(s + 16384 + so, al + go);
        cp16(s + 32768 + so, bh + go);
        cp16(s + 49152 + so, bl + go);
    }
    CP_COMMIT();
}

__global__ __launch_bounds__(256, 1) void gemm_kernel() {
    extern __shared__ char smem[];
    const uint32_t sb    = smem_u32(smem);
    const uint32_t tiles = (sb + 1023) & ~1023u;

    const int tid  = threadIdx.x;
    const int wid  = tid >> 5;
    const int lane = tid & 31;
    const int m0 = blockIdx.y * BM;
    const int n0 = blockIdx.x * BN;
    const int z  = blockIdx.z;                     // K-split index
    const int c0 = z * NCHUNK_SPLIT;               // first chunk
    const int wm = (wid >> 2) * 64;
    const int wn = (wid & 3) * 32;
    const int lr = lane & 15;
    const int lc = lane >> 4;

    const __nv_bfloat16* Ah = g_Ahi + (size_t)m0 * KDIM;
    const __nv_bfloat16* Al = g_Alo + (size_t)m0 * KDIM;
    const __nv_bfloat16* Bh = g_Whi + (size_t)n0 * KDIM;
    const __nv_bfloat16* Bl = g_Wlo + (size_t)n0 * KDIM;

    float acc[4][4][4];                 // [m16-tile][n8-tile][frag]
#pragma unroll
    for (int i = 0; i < 4; i++)
#pragma unroll
        for (int j = 0; j < 4; j++)
#pragma unroll
            for (int r = 0; r < 4; r++) acc[i][j][r] = 0.f;

    load_chunk(tiles, 0, Ah, Al, Bh, Bl, c0 * BK, tid);
    load_chunk(tiles, 1, Ah, Al, Bh, Bl, (c0 + 1) * BK, tid);

    for (int ch = 0; ch < NCHUNK_SPLIT; ch++) {
        if (ch >= NCHUNK_SPLIT - 2) { CP_WAIT0(); } else { CP_WAIT1(); }
        __syncthreads();

        // stage (ch+2)%3 == (ch-1)%3 fully consumed pre-barrier: refill now so
        // the async engine runs underneath the MMA block.
        if (ch + 2 < NCHUNK_SPLIT)
            load_chunk(tiles, (ch + 2) % NSTAGE, Ah, Al, Bh, Bl,
                       (c0 + ch + 2) * BK, tid);

        const uint32_t base = tiles + (ch % NSTAGE) * STAGE_BYTES;
#pragma unroll
        for (int ks = 0; ks < 4; ks++) {
            uint32_t aH[16], aL[16], bH[8], bL[8];
            const uint32_t kb = (uint32_t)(ks * 32 + lc * 16);
#pragma unroll
            for (int i = 0; i < 4; i++) {
                const uint32_t off = SWZ((uint32_t)((wm + i * 16 + lr) * 128) + kb);
                ldsm4(aH + 4 * i, base +         off);
                ldsm4(aL + 4 * i, base + 16384 + off);
            }
#pragma unroll
            for (int j = 0; j < 2; j++) {
                const uint32_t off = SWZ((uint32_t)((wn + j * 16 + lr) * 128) + kb);
                ldsm4(bH + 4 * j, base + 32768 + off);
                ldsm4(bL + 4 * j, base + 49152 + off);
            }
            // 3 split passes: hi*hi, hi*lo, lo*hi (lo*lo dropped, ~2^-16)
#pragma unroll
            for (int i = 0; i < 4; i++) {
#pragma unroll
                for (int j = 0; j < 2; j++) {
                    // x4 ldmatrix: r0=(rows0-7,k0-7), r1=(rows8-15,k0-7),
                    //              r2=(rows0-7,k8-15), r3=(rows8-15,k8-15)
                    mma16816(acc[i][2 * j],     aH + 4 * i, bH[4 * j],     bH[4 * j + 2]);
                    mma16816(acc[i][2 * j + 1], aH + 4 * i, bH[4 * j + 1], bH[4 * j + 3]);
                    mma16816(acc[i][2 * j],     aH + 4 * i, bL[4 * j],     bL[4 * j + 2]);
                    mma16816(acc[i][2 * j + 1], aH + 4 * i, bL[4 * j + 1], bL[4 * j + 3]);
                    mma16816(acc[i][2 * j],     aL + 4 * i, bH[4 * j],     bH[4 * j + 2]);
                    mma16816(acc[i][2 * j + 1], aL + 4 * i, bH[4 * j + 1], bH[4 * j + 3]);
                }
            }
        }
    }

    // Epilogue: plain coalesced partial stores (no atomics).
    float* P = g_part + (size_t)z * MROWS * DO;
    const int er = lane >> 2;
    const int ec = (lane & 3) * 2;
#pragma unroll
    for (int i = 0; i < 4; i++) {
#pragma unroll
        for (int jj = 0; jj < 4; jj++) {
            const int row = m0 + wm + i * 16 + er;
            const int col = n0 + wn + jj * 8 + ec;
            *(float2*)(P + (size_t)row * DO + col) =
                make_float2(acc[i][jj][0], acc[i][jj][1]);
            *(float2*)(P + (size_t)(row + 8) * DO + col) =
                make_float2(acc[i][jj][2], acc[i][jj][3]);
        }
    }
}

// ---------------------------------------------------------------------------
// Kernel 3: reduce 4 split-K partial planes into C (grid-stride)
// ---------------------------------------------------------------------------
__global__ void reduce_kernel(float* __restrict__ C) {
    const size_t NPL = (size_t)MROWS * DO;
    const size_t stride = (size_t)gridDim.x * blockDim.x * 4;
    for (size_t i = ((size_t)blockIdx.x * blockDim.x + threadIdx.x) * 4;
         i < NPL; i += stride) {
        float4 a = *(const float4*)(g_part + i);
        float4 b = *(const float4*)(g_part + NPL + i);
        float4 c = *(const float4*)(g_part + 2 * NPL + i);
        float4 d = *(const float4*)(g_part + 3 * NPL + i);
        float4 o;
        o.x = (a.x + b.x) + (c.x + d.x);
        o.y = (a.y + b.y) + (c.y + d.y);
        o.z = (a.z + b.z) + (c.z + d.z);
        o.w = (a.w + b.w) + (c.w + d.w);
        *(float4*)(C + i) = o;
    }
}

// ---------------------------------------------------------------------------
extern "C" void kernel_launch(void* const* d_in, const int* in_sizes, int n_in,
                              void* d_out, int out_size) {
    (void)in_sizes; (void)n_in; (void)out_size;
    const float* x    = (const float*)d_in[0];   // (B, T, DI)
    const float* filt = (const float*)d_in[1];   // (T, NF)
    const float* Mw   = (const float*)d_in[2];   // (NF, DO, DI)
    float*       out  = (float*)d_out;           // (B, T, DO)

    cudaFuncSetAttribute(gemm_kernel,
                         cudaFuncAttributeMaxDynamicSharedMemorySize, SMEM_TOTAL);

    convert_w_kernel<<<(NF * DO * DI) / 256, 256>>>(Mw);
    band_sum_kernel<<<dim3(NF, B_, 4 * NBANDT), 128>>>(x, filt);
    band_prefix_kernel<<<(B_ * KDIM) / 256, 256>>>();
    scan_kernel<<<dim3(NF, B_, 4 * NBANDT), 128>>>(x, filt);
    gemm_kernel<<<dim3(DO / BN, MROWS / BM, KSPLIT), 256, SMEM_TOTAL>>>();
    reduce_kernel<<<1024, 256>>>(out);
}

// round 16
// speedup vs baseline: 2.0599x; 1.0247x over previous
#include <cuda_runtime.h>
#include <cuda_bf16.h>
#include <cstdint>

#define B_    4
#define T_    2048
#define DI    512
#define DO    512
#define NF    24
#define KDIM  (NF * DI)      // 12288
#define MROWS (B_ * T_)      // 8192
#define NBANDT 16            // t-bands per sequence (128 steps each)

#define BM 128
#define BN 128
#define BK 64
#define KSPLIT 4
#define NCHUNK_SPLIT (KDIM / BK / KSPLIT)   // 48 chunks per CTA
#define STAGE_BYTES 65536    // Ahi 16K + Alo 16K + Bhi 16K + Blo 16K
#define NSTAGE 3
#define SMEM_TOTAL (NSTAGE * STAGE_BYTES + 1024)

// bf16 hi/lo split operands
static __device__ __nv_bfloat16 g_Ahi[(size_t)MROWS * KDIM];
static __device__ __nv_bfloat16 g_Alo[(size_t)MROWS * KDIM];
static __device__ __nv_bfloat16 g_Whi[(size_t)DO * KDIM];   // [o][n*DI+f]  (col-major B)
static __device__ __nv_bfloat16 g_Wlo[(size_t)DO * KDIM];
// split-K partials [KSPLIT][MROWS][DO] fp32 (67 MB)
static __device__ float g_part[(size_t)KSPLIT * MROWS * DO];
// scan band sums / exclusive prefixes [B*16][KDIM] fp32 (3.1 MB each)
static __device__ float g_band[(size_t)B_ * NBANDT * KDIM];
static __device__ float g_S0[(size_t)B_ * NBANDT * KDIM];

// ---------------------------------------------------------------------------
// helpers (base sm_80/90 PTX only — sm_103 w/o 'a' rejects tcgen05; IMMA
// measured 4x slower than HMMA; 3-pass bf16 mma.sync is the hardware floor)
// ---------------------------------------------------------------------------
__device__ __forceinline__ uint32_t smem_u32(const void* p) {
    uint32_t a;
    asm("{ .reg .u64 t; cvta.to.shared.u64 t, %1; cvt.u32.u64 %0, t; }"
        : "=r"(a) : "l"(p));
    return a;
}
__device__ __forceinline__ void cp16(uint32_t s, const void* g) {
    asm volatile("cp.async.cg.shared.global [%0], [%1], 16;\n"
                 :: "r"(s), "l"(g) : "memory");
}
#define CP_COMMIT() asm volatile("cp.async.commit_group;\n" ::: "memory")
#define CP_WAIT1()  asm volatile("cp.async.wait_group 1;\n" ::: "memory")
#define CP_WAIT0()  asm volatile("cp.async.wait_group 0;\n" ::: "memory")
#define SWZ(x) ((x) ^ (((x) >> 3) & 0x70))

__device__ __forceinline__ void ldsm4(uint32_t* r, uint32_t addr) {
    asm volatile("ldmatrix.sync.aligned.m8n8.x4.shared.b16 {%0,%1,%2,%3}, [%4];"
                 : "=r"(r[0]), "=r"(r[1]), "=r"(r[2]), "=r"(r[3]) : "r"(addr));
}
__device__ __forceinline__ void mma16816(float* d, const uint32_t* a,
                                         uint32_t b0, uint32_t b1) {
    asm volatile(
        "mma.sync.aligned.m16n8k16.row.col.f32.bf16.bf16.f32 "
        "{%0,%1,%2,%3}, {%4,%5,%6,%7}, {%8,%9}, {%0,%1,%2,%3};"
        : "+f"(d[0]), "+f"(d[1]), "+f"(d[2]), "+f"(d[3])
        : "r"(a[0]), "r"(a[1]), "r"(a[2]), "r"(a[3]), "r"(b0), "r"(b1));
}
// pack two fp32 -> bf16x2 (lo word = first arg, matching f, f+1 order)
__device__ __forceinline__ uint32_t pack_bf2(float a, float b) {
    __nv_bfloat162 t = __floats2bfloat162_rn(a, b);
    uint32_t u;
    *(__nv_bfloat162*)&u = t;
    return u;
}

// ---------------------------------------------------------------------------
// Kernel 0: convert M_weights (n,o,f) fp32 -> W_hi/W_lo bf16 [o][n*DI+f]
// 2 f-lanes per thread: float2 in, bf16x2 out (4B stores)
// ---------------------------------------------------------------------------
__global__ void convert_w_kernel(const float* __restrict__ Mw) {
    size_t i = ((size_t)blockIdx.x * 256 + threadIdx.x) * 2;   // over NF*DO*DI
    int f = (int)(i & (DI - 1));
    int o = (int)((i >> 9) & (DO - 1));
    int n = (int)(i >> 18);
    float2 v = *(const float2*)(Mw + i);
    __nv_bfloat16 h0 = __float2bfloat16(v.x);
    __nv_bfloat16 h1 = __float2bfloat16(v.y);
    float l0 = v.x - __bfloat162float(h0);
    float l1 = v.y - __bfloat162float(h1);
    size_t d = (size_t)o * KDIM + (size_t)n * DI + f;
    *(uint32_t*)(g_Whi + d) = pack_bf2(__bfloat162float(h0), __bfloat162float(h1));
    *(uint32_t*)(g_Wlo + d) = pack_bf2(l0, l1);
}

// ---------------------------------------------------------------------------
// Scan phase A: per-band sums  bandsum[b*16+j][n*DI+f] = sum_{t in band} phi*x
// grid (NF, B_, 64): z = band*4 + fchunk; block 128
// ---------------------------------------------------------------------------
__global__ void band_sum_kernel(const float* __restrict__ x,
                                const float* __restrict__ filt) {
    __shared__ float ph[128];
    const int n    = blockIdx.x;
    const int b    = blockIdx.y;
    const int band = blockIdx.z >> 2;
    const int fc   = blockIdx.z & 3;
    const int f    = fc * 128 + threadIdx.x;
    const int t0   = band * 128;

    if (threadIdx.x < 128)
        ph[threadIdx.x] = filt[(t0 + threadIdx.x) * NF + n];
    __syncthreads();

    const float* xb = x + ((size_t)b * T_ + t0) * DI + f;
    float s = 0.f;
#pragma unroll 8
    for (int i = 0; i < 128; i++)
        s = fmaf(ph[i], xb[(size_t)i * DI], s);
    g_band[(size_t)(b * NBANDT + band) * KDIM + n * DI + f] = s;
}

// ---------------------------------------------------------------------------
// Scan phase B: exclusive prefix over the 16 bands of each (b,k) chain
// ---------------------------------------------------------------------------
__global__ void band_prefix_kernel() {
    const size_t c = (size_t)blockIdx.x * 256 + threadIdx.x;  // over B_*KDIM
    const int b = (int)(c / KDIM);
    const int k = (int)(c % KDIM);
    float run = 0.f;
#pragma unroll
    for (int j = 0; j < NBANDT; j++) {
        const size_t idx = (size_t)(b * NBANDT + j) * KDIM + k;
        const float v = g_band[idx];
        g_S0[idx] = run;
        run += v;
    }
}

// ---------------------------------------------------------------------------
// Scan phase C: within-band scan -> A_hi/A_lo bf16 [(b*T+t)][n*DI+f]
// grid (NF, B_, 32): z = band*2 + fchunk; block 128; 2 f-lanes per thread
// (float2 x loads, bf16x2 4-byte stores — halves store-issue/L1 wavefronts)
// ---------------------------------------------------------------------------
__global__ void scan_kernel(const float* __restrict__ x,
                            const float* __restrict__ filt) {
    __shared__ float ph[128];
    const int n    = blockIdx.x;
    const int b    = blockIdx.y;
    const int band = blockIdx.z >> 1;
    const int fc   = blockIdx.z & 1;
    const int f    = fc * 256 + threadIdx.x * 2;
    const int t0   = band * 128;

    ph[threadIdx.x] = filt[(t0 + threadIdx.x) * NF + n];
    __syncthreads();

    const float* xb = x + ((size_t)b * T_ + t0) * DI + f;
    const size_t base = ((size_t)b * T_ + t0) * KDIM + (size_t)n * DI + f;

    float2 sv = *(const float2*)(
        g_S0 + (size_t)(b * NBANDT + band) * KDIM + n * DI + f);
    float s0 = sv.x, s1 = sv.y;

#pragma unroll 4
    for (int i0 = 0; i0 < 128; i0 += 8) {
        float2 xv[8];
#pragma unroll
        for (int u = 0; u < 8; u++)
            xv[u] = *(const float2*)(xb + (size_t)(i0 + u) * DI);
#pragma unroll
        for (int u = 0; u < 8; u++) {
            const float p = ph[i0 + u];
            s0 = fmaf(p, xv[u].x, s0);
            s1 = fmaf(p, xv[u].y, s1);
            const float v0 = p * s0;
            const float v1 = p * s1;
            const __nv_bfloat16 h0 = __float2bfloat16(v0);
            const __nv_bfloat16 h1 = __float2bfloat16(v1);
            const float l0 = v0 - __bfloat162float(h0);
            const float l1 = v1 - __bfloat162float(h1);
            const size_t idx = base + (size_t)(i0 + u) * KDIM;
            *(uint32_t*)(g_Ahi + idx) =
                pack_bf2(__bfloat162float(h0), __bfloat162float(h1));
            *(uint32_t*)(g_Alo + idx) = pack_bf2(l0, l1);
        }
    }
}

// ---------------------------------------------------------------------------
// Kernel 2: split-bf16 GEMM via mma.sync — champion config + split-K/4.
// CTA 128x128, 256 threads (8 warps 2x4, 64x32 warp tiles), 3-stage cp.async.
// 1024 CTAs (6.92 waves, imbalance 1.012) each do 48 K-chunks; partials out.
// ---------------------------------------------------------------------------
__device__ __forceinline__ void load_chunk(uint32_t tiles, int stage,
                                           const __nv_bfloat16* Ah,
                                           const __nv_bfloat16* Al,
                                           const __nv_bfloat16* Bh,
                                           const __nv_bfloat16* Bl,
                                           int k0, int tid) {
    const uint32_t s = tiles + stage * STAGE_BYTES;
    const __nv_bfloat16* ah = Ah + k0;
    const __nv_bfloat16* al = Al + k0;
    const __nv_bfloat16* bh = Bh + k0;
    const __nv_bfloat16* bl = Bl + k0;
    // each subtile: 128 rows x 128B = 1024 x 16B units; 256 threads -> 4 each
#pragma unroll
    for (int j = 0; j < 4; j++) {
        const int u = j * 256 + tid;
        const int r = u >> 3, seg = u & 7;
        const uint32_t so = SWZ((uint32_t)(r * 128 + seg * 16));
        const size_t go = (size_t)r * KDIM + seg * 8;
        cp16(s +         so, ah + go);
        cp16(s + 16384 + so, al + go);
        cp16(s + 32768 + so, bh + go);
        cp16(s + 49152 + so, bl + go);
    }
    CP_COMMIT();
}

__global__ __launch_bounds__(256, 1) void gemm_kernel() {
    extern __shared__ char smem[];
    const uint32_t sb    = smem_u32(smem);
    const uint32_t tiles = (sb + 1023) & ~1023u;

    const int tid  = threadIdx.x;
    const int wid  = tid >> 5;
    const int lane = tid & 31;
    const int m0 = blockIdx.y * BM;
    const int n0 = blockIdx.x * BN;
    const int z  = blockIdx.z;                     // K-split index
    const int c0 = z * NCHUNK_SPLIT;               // first chunk
    const int wm = (wid >> 2) * 64;
    const int wn = (wid & 3) * 32;
    const int lr = lane & 15;
    const int lc = lane >> 4;

    const __nv_bfloat16* Ah = g_Ahi + (size_t)m0 * KDIM;
    const __nv_bfloat16* Al = g_Alo + (size_t)m0 * KDIM;
    const __nv_bfloat16* Bh = g_Whi + (size_t)n0 * KDIM;
    const __nv_bfloat16* Bl = g_Wlo + (size_t)n0 * KDIM;

    float acc[4][4][4];                 // [m16-tile][n8-tile][frag]
#pragma unroll
    for (int i = 0; i < 4; i++)
#pragma unroll
        for (int j = 0; j < 4; j++)
#pragma unroll
            for (int r = 0; r < 4; r++) acc[i][j][r] = 0.f;

    load_chunk(tiles, 0, Ah, Al, Bh, Bl, c0 * BK, tid);
    load_chunk(tiles, 1, Ah, Al, Bh, Bl, (c0 + 1) * BK, tid);

    for (int ch = 0; ch < NCHUNK_SPLIT; ch++) {
        if (ch >= NCHUNK_SPLIT - 2) { CP_WAIT0(); } else { CP_WAIT1(); }
        __syncthreads();

        // stage (ch+2)%3 == (ch-1)%3 fully consumed pre-barrier: refill now so
        // the async engine runs underneath the MMA block.
        if (ch + 2 < NCHUNK_SPLIT)
            load_chunk(tiles, (ch + 2) % NSTAGE, Ah, Al, Bh, Bl,
                       (c0 + ch + 2) * BK, tid);

        const uint32_t base = tiles + (ch % NSTAGE) * STAGE_BYTES;
#pragma unroll
        for (int ks = 0; ks < 4; ks++) {
            uint32_t aH[16], aL[16], bH[8], bL[8];
            const uint32_t kb = (uint32_t)(ks * 32 + lc * 16);
#pragma unroll
            for (int i = 0; i < 4; i++) {
                const uint32_t off = SWZ((uint32_t)((wm + i * 16 + lr) * 128) + kb);
                ldsm4(aH + 4 * i, base +         off);
                ldsm4(aL + 4 * i, base + 16384 + off);
            }
#pragma unroll
            for (int j = 0; j < 2; j++) {
                const uint32_t off = SWZ((uint32_t)((wn + j * 16 + lr) * 128) + kb);
                ldsm4(bH + 4 * j, base + 32768 + off);
                ldsm4(bL + 4 * j, base + 49152 + off);
            }
            // 3 split passes: hi*hi, hi*lo, lo*hi (lo*lo dropped, ~2^-16)
#pragma unroll
            for (int i = 0; i < 4; i++) {
#pragma unroll
                for (int j = 0; j < 2; j++) {
                    // x4 ldmatrix: r0=(rows0-7,k0-7), r1=(rows8-15,k0-7),
                    //              r2=(rows0-7,k8-15), r3=(rows8-15,k8-15)
                    mma16816(acc[i][2 * j],     aH + 4 * i, bH[4 * j],     bH[4 * j + 2]);
                    mma16816(acc[i][2 * j + 1], aH + 4 * i, bH[4 * j + 1], bH[4 * j + 3]);
                    mma16816(acc[i][2 * j],     aH + 4 * i, bL[4 * j],     bL[4 * j + 2]);
                    mma16816(acc[i][2 * j + 1], aH + 4 * i, bL[4 * j + 1], bL[4 * j + 3]);
                    mma16816(acc[i][2 * j],     aL + 4 * i, bH[4 * j],     bH[4 * j + 2]);
                    mma16816(acc[i][2 * j + 1], aL + 4 * i, bH[4 * j + 1], bH[4 * j + 3]);
                }
            }
        }
    }

    // Epilogue: plain coalesced partial stores (no atomics).
    float* P = g_part + (size_t)z * MROWS * DO;
    const int er = lane >> 2;
    const int ec = (lane & 3) * 2;
#pragma unroll
    for (int i = 0; i < 4; i++) {
#pragma unroll
        for (int jj = 0; jj < 4; jj++) {
            const int row = m0 + wm + i * 16 + er;
            const int col = n0 + wn + jj * 8 + ec;
            *(float2*)(P + (size_t)row * DO + col) =
                make_float2(acc[i][jj][0], acc[i][jj][1]);
            *(float2*)(P + (size_t)(row + 8) * DO + col) =
                make_float2(acc[i][jj][2], acc[i][jj][3]);
        }
    }
}

// ---------------------------------------------------------------------------
// Kernel 3: reduce 4 split-K partial planes into C (grid-stride)
// ---------------------------------------------------------------------------
__global__ void reduce_kernel(float* __restrict__ C) {
    const size_t NPL = (size_t)MROWS * DO;
    const size_t stride = (size_t)gridDim.x * blockDim.x * 4;
    for (size_t i = ((size_t)blockIdx.x * blockDim.x + threadIdx.x) * 4;
         i < NPL; i += stride) {
        float4 a = *(const float4*)(g_part + i);
        float4 b = *(const float4*)(g_part + NPL + i);
        float4 c = *(const float4*)(g_part + 2 * NPL + i);
        float4 d = *(const float4*)(g_part + 3 * NPL + i);
        float4 o;
        o.x = (a.x + b.x) + (c.x + d.x);
        o.y = (a.y + b.y) + (c.y + d.y);
        o.z = (a.z + b.z) + (c.z + d.z);
        o.w = (a.w + b.w) + (c.w + d.w);
        *(float4*)(C + i) = o;
    }
}

// ---------------------------------------------------------------------------
extern "C" void kernel_launch(void* const* d_in, const int* in_sizes, int n_in,
                              void* d_out, int out_size) {
    (void)in_sizes; (void)n_in; (void)out_size;
    const float* x    = (const float*)d_in[0];   // (B, T, DI)
    const float* filt = (const float*)d_in[1];   // (T, NF)
    const float* Mw   = (const float*)d_in[2];   // (NF, DO, DI)
    float*       out  = (float*)d_out;           // (B, T, DO)

    cudaFuncSetAttribute(gemm_kernel,
                         cudaFuncAttributeMaxDynamicSharedMemorySize, SMEM_TOTAL);

    convert_w_kernel<<<(NF * DO * DI) / 512, 256>>>(Mw);
    band_sum_kernel<<<dim3(NF, B_, 4 * NBANDT), 128>>>(x, filt);
    band_prefix_kernel<<<(B_ * KDIM) / 256, 256>>>();
    scan_kernel<<<dim3(NF, B_, 2 * NBANDT), 128>>>(x, filt);
    gemm_kernel<<<dim3(DO / BN, MROWS / BM, KSPLIT), 256, SMEM_TOTAL>>>();
    reduce_kernel<<<1024, 256>>>(out);
}